// round 9
// baseline (speedup 1.0000x reference)
#include <cuda_runtime.h>
#include <cuda_bf16.h>
#include <cstdint>

// Problem constants
#define B_    32
#define C_    256
#define HW_   1024
#define N_    32768          // B_*HW_
#define K_    1024
#define QSIZE 8388608        // B_*C_*HW_
#define KEXT  768            // 3 bf16 planes concatenated along K

__device__ float g_enorm[K_];
__device__ float g_apart[4 * N_];                     // per-c-block partial |z|^2
__device__ float g_loss;
__device__ __nv_bfloat16 g_Aext[(size_t)N_ * KEXT];   // x rows, [n][768]
__device__ __nv_bfloat16 g_Bext[(size_t)K_ * KEXT];   // codebook, [k][768]

// ---------------------------------------------------------------------------
// PTX helpers (plain PTX only: valid on compute_103 base target)
// ---------------------------------------------------------------------------
__device__ __forceinline__ uint32_t smem_u32(const void* p) {
    uint32_t a;
    asm("{ .reg .u64 t; cvta.to.shared.u64 t, %1; cvt.u32.u64 %0, t; }" : "=r"(a) : "l"(p));
    return a;
}
__device__ __forceinline__ void cp16(uint32_t daddr, const void* g) {
    asm volatile("cp.async.cg.shared.global [%0], [%1], 16;" :: "r"(daddr), "l"(g));
}
#define CP_COMMIT()  asm volatile("cp.async.commit_group;")
#define CP_WAIT0()   asm volatile("cp.async.wait_group 0;")

__device__ __forceinline__ void ldsm4(uint32_t* r, uint32_t addr) {
    asm volatile("ldmatrix.sync.aligned.m8n8.x4.shared.b16 {%0,%1,%2,%3}, [%4];"
        : "=r"(r[0]), "=r"(r[1]), "=r"(r[2]), "=r"(r[3]) : "r"(addr));
}
__device__ __forceinline__ void mma16816(float* d, const uint32_t* a, const uint32_t* b) {
    asm volatile(
        "mma.sync.aligned.m16n8k16.row.col.f32.bf16.bf16.f32 "
        "{%0,%1,%2,%3},{%4,%5,%6,%7},{%8,%9},{%0,%1,%2,%3};"
        : "+f"(d[0]), "+f"(d[1]), "+f"(d[2]), "+f"(d[3])
        : "r"(a[0]), "r"(a[1]), "r"(a[2]), "r"(a[3]), "r"(b[0]), "r"(b[1]));
}

// ---------------------------------------------------------------------------
// Prep kernels
// ---------------------------------------------------------------------------
__global__ void zero_loss_kernel() { g_loss = 0.0f; }

__global__ void enorm_kernel(const float* __restrict__ cb) {
    int k = blockIdx.x * blockDim.x + threadIdx.x;
    if (k < K_) {
        const float4* row = reinterpret_cast<const float4*>(cb + (size_t)k * C_);
        float s = 0.f;
        #pragma unroll
        for (int i = 0; i < C_ / 4; ++i) {
            float4 v = row[i];
            s += v.x * v.x + v.y * v.y + v.z * v.z + v.w * v.w;
        }
        g_enorm[k] = s;
    }
}

__global__ void finalize_kernel(float* __restrict__ out) {
    out[QSIZE] = 1.25f * g_loss * (1.0f / (float)QSIZE);
}

// Split codebook rows into 3 bf16 planes at k-offsets 0 / 256 / 512.
__global__ void prep_cb_kernel(const float* __restrict__ cb) {
    int i = blockIdx.x * blockDim.x + threadIdx.x;   // 0 .. 262143
    int row = i >> 8, c = i & 255;
    float v = cb[i];
    __nv_bfloat16 h = __float2bfloat16_rn(v);
    float r = v - __bfloat162float(h);
    __nv_bfloat16 m = __float2bfloat16_rn(r);
    float r2 = r - __bfloat162float(m);
    __nv_bfloat16 l = __float2bfloat16_rn(r2);
    size_t o = (size_t)row * KEXT + c;
    g_Bext[o] = h; g_Bext[o + 256] = m; g_Bext[o + 512] = l;
}

// Transpose x -> A_ext bf16 planes + deterministic per-c-block |z|^2 partials.
__global__ void prep_x_kernel(const float* __restrict__ x) {
    __shared__ float tile[64][65];
    __shared__ float w2[8];
    int bid = blockIdx.x;          // 2048 blocks
    int b   = bid >> 6;
    int rem = bid & 63;
    int cb4 = rem >> 4;            // c-block 0..3
    int c0  = cb4 << 6;
    int hw0 = (rem & 15) << 6;
    int tid = threadIdx.x;
    int lane = tid & 31, wid = tid >> 5;

    #pragma unroll
    for (int i = 0; i < 16; ++i) {
        int cc = i * 4 + (tid >> 6);
        int hw = tid & 63;
        tile[cc][hw] = x[((size_t)b * C_ + c0 + cc) * HW_ + hw0 + hw];
    }
    __syncthreads();
    #pragma unroll
    for (int i = 0; i < 16; ++i) {
        int hh = i * 4 + (tid >> 6);
        int ci = tid & 63;
        float v = tile[ci][hh];
        __nv_bfloat16 h = __float2bfloat16_rn(v);
        float r = v - __bfloat162float(h);
        __nv_bfloat16 m = __float2bfloat16_rn(r);
        float r2 = r - __bfloat162float(m);
        __nv_bfloat16 l = __float2bfloat16_rn(r2);
        size_t o = (size_t)(b * HW_ + hw0 + hh) * KEXT + c0 + ci;
        g_Aext[o] = h; g_Aext[o + 256] = m; g_Aext[o + 512] = l;

        // partial |z|^2 over this 64-c block (deterministic order)
        float s = v * v;
        #pragma unroll
        for (int off = 16; off; off >>= 1) s += __shfl_xor_sync(0xffffffffu, s, off);
        if (lane == 0) w2[wid] = s;
        __syncthreads();
        if (lane == 0 && !(wid & 1))
            g_apart[cb4 * N_ + b * HW_ + hw0 + hh] = w2[wid] + w2[wid + 1];
        __syncthreads();
    }
}

// ---------------------------------------------------------------------------
// Fused main kernel: 256 CTAs x (128 rows, all 1024 codes).
// bf16 HMMA GEMM (K=768 planes) -> per-chunk approx argmin + candidate
// superset -> in-CTA exact fp32 recheck -> gather + straight-through + loss.
// ---------------------------------------------------------------------------
#define APITCH 72
#define ABUF_B (128 * APITCH * 2)          // 18432
#define BBUF_B (256 * APITCH * 2)          // 36864
#define SM_GEMM (2 * ABUF_B + 2 * BBUF_B)  // 110592
#define CAP   24
#define DELTA 2e-3f

__device__ __forceinline__ void load_chunk(uint32_t smAbuf, uint32_t smBbuf,
                                           const __nv_bfloat16* Ag,
                                           const __nv_bfloat16* Bg,
                                           int kof, int tid)
{
    #pragma unroll
    for (int j = 0; j < 4; ++j) {
        int p = tid + j * 256, row = p >> 3, kp = (p & 7) << 3;
        cp16(smAbuf + (uint32_t)((row * APITCH + kp) * 2),
             Ag + (size_t)row * KEXT + kof + kp);
    }
    #pragma unroll
    for (int j = 0; j < 8; ++j) {
        int p = tid + j * 256, row = p >> 3, kp = (p & 7) << 3;
        cp16(smBbuf + (uint32_t)((row * APITCH + kp) * 2),
             Bg + (size_t)row * KEXT + kof + kp);
    }
}

__global__ __launch_bounds__(256, 1)
void vq_main_kernel(const float* __restrict__ x,
                    const float* __restrict__ cb,
                    float* __restrict__ out)
{
    extern __shared__ __align__(16) char dsm[];
    const uint32_t smA = smem_u32(dsm);
    const uint32_t smB = smA + 2 * ABUF_B;

    __shared__ float sEn[K_];
    __shared__ float sAv[128];
    __shared__ unsigned long long rowmin[128];
    __shared__ unsigned long long finalmin[128];
    __shared__ int   cnt[128];
    __shared__ int   candK[128][CAP];
    __shared__ int   srow[128];
    __shared__ float wsum[8];

    const int tid  = threadIdx.x;
    const int lane = tid & 31;
    const int wid  = tid >> 5;
    const int wm   = wid >> 2;
    const int wn   = wid & 3;

    const int blk = blockIdx.x;
    const int m0  = blk << 7;
    const int b   = blk >> 3;
    const int hw0 = (blk & 7) << 7;

    #pragma unroll
    for (int i = 0; i < 4; ++i) sEn[i * 256 + tid] = g_enorm[i * 256 + tid];
    if (tid < 128) {
        int n = m0 + tid;
        float a = ((g_apart[n] + g_apart[N_ + n]) + g_apart[2 * N_ + n]) + g_apart[3 * N_ + n];
        sAv[tid] = a;
        rowmin[tid]   = 0xFFFFFFFFFFFFFFFFull;
        finalmin[tid] = 0xFFFFFFFFFFFFFFFFull;
        cnt[tid] = 0;
    }
    __syncthreads();

    const __nv_bfloat16* Ag = g_Aext + (size_t)m0 * KEXT;

    const uint32_t aAddr0 = smA + (uint32_t)(((wm * 64 + (lane & 15)) * APITCH + ((lane >> 4) << 3)) * 2);
    const uint32_t bAddr0 = smB + (uint32_t)(((wn * 64 + (lane & 7) + ((lane >> 4) << 3)) * APITCH
                                              + (((lane >> 3) & 1) << 3)) * 2);

    // prologue: (nc=0, kc=0) -> buffer 0
    load_chunk(smA, smB, Ag, g_Bext, 0, tid);
    CP_COMMIT();

    const int rb  = (wm << 6) + (lane >> 2);          // local row base
    const int cl0 = (wn << 6) + ((lane & 3) << 1);    // col base within chunk

    for (int nc = 0; nc < 4; ++nc) {
        float acc[4][8][4];
        #pragma unroll
        for (int mf = 0; mf < 4; ++mf)
            #pragma unroll
            for (int nf = 0; nf < 8; ++nf)
                #pragma unroll
                for (int q = 0; q < 4; ++q) acc[mf][nf][q] = 0.f;

        for (int kc = 0; kc < 12; ++kc) {
            CP_WAIT0();
            __syncthreads();

            // prefetch next (nc2, kc2)
            {
                int nc2 = (kc == 11) ? nc + 1 : nc;
                int kc2 = (kc == 11) ? 0 : kc + 1;
                if (nc2 < 4) {
                    int nb = (kc + 1) & 1;
                    load_chunk(smA + nb * ABUF_B, smB + nb * BBUF_B,
                               Ag, g_Bext + ((size_t)(nc2 << 8)) * KEXT, kc2 << 6, tid);
                    CP_COMMIT();
                }
            }

            const int buf = kc & 1;
            const uint32_t aB = aAddr0 + (uint32_t)(buf * ABUF_B);
            const uint32_t bB = bAddr0 + (uint32_t)(buf * BBUF_B);

            #pragma unroll
            for (int ks = 0; ks < 4; ++ks) {
                uint32_t a[4][4], bfr[4][4];
                #pragma unroll
                for (int mf = 0; mf < 4; ++mf)
                    ldsm4(a[mf], aB + (uint32_t)(mf * 16 * APITCH * 2 + ks * 32));
                #pragma unroll
                for (int nb2 = 0; nb2 < 4; ++nb2)
                    ldsm4(bfr[nb2], bB + (uint32_t)(nb2 * 16 * APITCH * 2 + ks * 32));
                #pragma unroll
                for (int mf = 0; mf < 4; ++mf)
                    #pragma unroll
                    for (int nf = 0; nf < 8; ++nf)
                        mma16816(acc[mf][nf], a[mf], &bfr[nf >> 1][(nf & 1) << 1]);
            }
        }

        // ---- chunk epilogue: quantized approx distances + running argmin ----
        const int cb0 = (nc << 8) + cl0;
        #pragma unroll
        for (int mf = 0; mf < 4; ++mf) {
            #pragma unroll
            for (int half = 0; half < 2; ++half) {
                int lrow = rb + mf * 16 + half * 8;
                float a = sAv[lrow];
                unsigned long long lm = 0xFFFFFFFFFFFFFFFFull;
                #pragma unroll
                for (int nf = 0; nf < 8; ++nf) {
                    int col = cb0 + nf * 8;
                    float s0 = (a + sEn[col])     - 2.0f * acc[mf][nf][half * 2 + 0];
                    float s1 = (a + sEn[col + 1]) - 2.0f * acc[mf][nf][half * 2 + 1];
                    acc[mf][nf][half * 2 + 0] = s0;
                    acc[mf][nf][half * 2 + 1] = s1;
                    unsigned long long p;
                    p = ((unsigned long long)__float_as_uint(s0) << 32) | (unsigned)col;
                    if (p < lm) lm = p;
                    p = ((unsigned long long)__float_as_uint(s1) << 32) | (unsigned)(col + 1);
                    if (p < lm) lm = p;
                }
                atomicMin(&rowmin[lrow], lm);
            }
        }
        __syncthreads();
        // candidate superset collection (running_min >= final_min => safe)
        #pragma unroll
        for (int mf = 0; mf < 4; ++mf) {
            #pragma unroll
            for (int half = 0; half < 2; ++half) {
                int lrow = rb + mf * 16 + half * 8;
                float thr = __uint_as_float((unsigned)(rowmin[lrow] >> 32)) + DELTA;
                #pragma unroll
                for (int nf = 0; nf < 8; ++nf) {
                    int col = cb0 + nf * 8;
                    if (acc[mf][nf][half * 2 + 0] <= thr) {
                        int pos = atomicAdd(&cnt[lrow], 1);
                        if (pos < CAP) candK[lrow][pos] = col;
                    }
                    if (acc[mf][nf][half * 2 + 1] <= thr) {
                        int pos = atomicAdd(&cnt[lrow], 1);
                        if (pos < CAP) candK[lrow][pos] = col + 1;
                    }
                }
            }
        }
    }
    __syncthreads();

    // ---- exact fp32 recheck of candidates (2 threads per row) -------------
    {
        const int row = tid >> 1;
        const int j0  = tid & 1;
        int nct = cnt[row]; if (nct > CAP) nct = CAP;
        const float a = sAv[row];
        const __nv_bfloat16* ar = g_Aext + (size_t)(m0 + row) * KEXT;
        unsigned long long eb = 0xFFFFFFFFFFFFFFFFull;
        for (int j = j0; j < nct; j += 2) {
            int k = candK[row][j];
            const float* cr = cb + (size_t)k * C_;
            float m2 = 0.f;
            #pragma unroll 8
            for (int c = 0; c < C_; ++c) {
                float xr = __bfloat162float(ar[c])
                         + __bfloat162float(ar[c + 256])
                         + __bfloat162float(ar[c + 512]);
                m2 = fmaf(xr, cr[c], m2);
            }
            float s = (a + sEn[k]) - 2.0f * m2;
            unsigned long long p =
                ((unsigned long long)__float_as_uint(s) << 32) | (unsigned)k;
            if (p < eb) eb = p;
        }
        atomicMin(&finalmin[row], eb);
    }
    __syncthreads();
    if (tid < 128) {
        int idx = (int)(unsigned)(finalmin[tid] & 0xFFFFFFFFull);
        srow[tid] = idx;
        out[QSIZE + 1 + m0 + tid] = (float)idx;
    }
    __syncthreads();

    // ---- gather + straight-through (x + fl(q - x)) + loss ------------------
    const float* xblk = x   + (size_t)b * (C_ * HW_) + hw0;
    float*       qblk = out + (size_t)b * (C_ * HW_) + hw0;
    float lsum = 0.f;
    #pragma unroll 4
    for (int it = 0; it < 32; ++it) {
        int l  = it * 256 + tid;
        int m4 = (l & 31) << 2;
        int c  = l >> 5;
        float4 xv = *reinterpret_cast<const float4*>(xblk + c * HW_ + m4);
        float q0 = __ldg(cb + (size_t)srow[m4 + 0] * C_ + c);
        float q1 = __ldg(cb + (size_t)srow[m4 + 1] * C_ + c);
        float q2 = __ldg(cb + (size_t)srow[m4 + 2] * C_ + c);
        float q3 = __ldg(cb + (size_t)srow[m4 + 3] * C_ + c);
        float d0 = q0 - xv.x, d1 = q1 - xv.y, d2 = q2 - xv.z, d3 = q3 - xv.w;
        float4 o;
        o.x = xv.x + d0; o.y = xv.y + d1; o.z = xv.z + d2; o.w = xv.w + d3;
        *reinterpret_cast<float4*>(qblk + c * HW_ + m4) = o;
        lsum += d0 * d0 + d1 * d1 + d2 * d2 + d3 * d3;
    }

    #pragma unroll
    for (int off = 16; off; off >>= 1)
        lsum += __shfl_xor_sync(0xffffffffu, lsum, off);
    if ((tid & 31) == 0) wsum[tid >> 5] = lsum;
    __syncthreads();
    if (tid == 0) {
        float s = 0.f;
        #pragma unroll
        for (int w = 0; w < 8; ++w) s += wsum[w];
        atomicAdd(&g_loss, s);
    }
}

extern "C" void kernel_launch(void* const* d_in, const int* in_sizes, int n_in,
                              void* d_out, int out_size) {
    (void)in_sizes; (void)n_in; (void)out_size;
    const float* x  = (const float*)d_in[0];
    const float* cb = (const float*)d_in[1];
    float* out = (float*)d_out;

    static bool attr_done = false;
    if (!attr_done) {
        cudaFuncSetAttribute(vq_main_kernel,
                             cudaFuncAttributeMaxDynamicSharedMemorySize, SM_GEMM);
        attr_done = true;
    }

    zero_loss_kernel<<<1, 1>>>();
    enorm_kernel<<<4, 256>>>(cb);
    prep_cb_kernel<<<1024, 256>>>(cb);
    prep_x_kernel<<<2048, 256>>>(x);
    vq_main_kernel<<<256, 256, SM_GEMM>>>(x, cb, out);
    finalize_kernel<<<1, 1>>>(out);
}

// round 10
// speedup vs baseline: 1.4143x; 1.4143x over previous
#include <cuda_runtime.h>
#include <cuda_fp16.h>
#include <cstdint>

// Problem constants
#define B_    32
#define C_    256
#define HW_   1024
#define N_    32768          // B_*HW_
#define K_    1024
#define QSIZE 8388608        // B_*C_*HW_
#define CAP   32
#define DELTA 2e-3f

__device__ float g_enorm[K_];
__device__ float g_apart[4 * N_];           // per-64c-block partial |z|^2
__device__ float g_loss;
__device__ int   g_idx[N_];
__device__ int   g_cnt[N_];
__device__ int   g_cand[(size_t)N_ * CAP];
__device__ __half g_Ah[(size_t)N_ * C_];    // x rows hi plane, [n][256]
__device__ __half g_Am[(size_t)N_ * C_];    // x rows residual plane
__device__ __half g_Bh[(size_t)K_ * C_];    // codebook hi plane, [k][256]

// ---------------------------------------------------------------------------
// PTX helpers
// ---------------------------------------------------------------------------
__device__ __forceinline__ uint32_t smem_u32(const void* p) {
    uint32_t a;
    asm("{ .reg .u64 t; cvta.to.shared.u64 t, %1; cvt.u32.u64 %0, t; }" : "=r"(a) : "l"(p));
    return a;
}
__device__ __forceinline__ void cp16(uint32_t daddr, const void* g) {
    asm volatile("cp.async.cg.shared.global [%0], [%1], 16;" :: "r"(daddr), "l"(g));
}
#define CP_COMMIT()  asm volatile("cp.async.commit_group;")
#define CP_WAIT0()   asm volatile("cp.async.wait_group 0;")

__device__ __forceinline__ void ldsm4(uint32_t* r, uint32_t addr) {
    asm volatile("ldmatrix.sync.aligned.m8n8.x4.shared.b16 {%0,%1,%2,%3}, [%4];"
        : "=r"(r[0]), "=r"(r[1]), "=r"(r[2]), "=r"(r[3]) : "r"(addr));
}
__device__ __forceinline__ void mma16816(float* d, const uint32_t* a, const uint32_t* b) {
    asm volatile(
        "mma.sync.aligned.m16n8k16.row.col.f32.f16.f16.f32 "
        "{%0,%1,%2,%3},{%4,%5,%6,%7},{%8,%9},{%0,%1,%2,%3};"
        : "+f"(d[0]), "+f"(d[1]), "+f"(d[2]), "+f"(d[3])
        : "r"(a[0]), "r"(a[1]), "r"(a[2]), "r"(a[3]), "r"(b[0]), "r"(b[1]));
}

// ---------------------------------------------------------------------------
// Prep kernels
// ---------------------------------------------------------------------------
__global__ void init_kernel() {
    int i = blockIdx.x * blockDim.x + threadIdx.x;
    if (i < N_) g_cnt[i] = 0;
    if (i == 0) g_loss = 0.0f;
}

__global__ void enorm_kernel(const float* __restrict__ cb) {
    int k = blockIdx.x * blockDim.x + threadIdx.x;
    if (k < K_) {
        const float4* row = reinterpret_cast<const float4*>(cb + (size_t)k * C_);
        float s = 0.f;
        #pragma unroll
        for (int i = 0; i < C_ / 4; ++i) {
            float4 v = row[i];
            s += v.x * v.x + v.y * v.y + v.z * v.z + v.w * v.w;
        }
        g_enorm[k] = s;
    }
}

__global__ void finalize_kernel(float* __restrict__ out) {
    out[QSIZE] = 1.25f * g_loss * (1.0f / (float)QSIZE);
}

// Codebook -> single fp16 hi plane (GEMM operand).
__global__ void prep_cb_kernel(const float* __restrict__ cb) {
    int i = blockIdx.x * blockDim.x + threadIdx.x;   // 0 .. 262143
    g_Bh[i] = __float2half_rn(cb[i]);
}

// Transpose x -> 2 fp16 planes [n][256] + deterministic |z|^2 partials.
__global__ void prep_x_kernel(const float* __restrict__ x) {
    __shared__ float tile[64][65];
    __shared__ float w2[8];
    int bid = blockIdx.x;          // 2048 blocks
    int b   = bid >> 6;
    int rem = bid & 63;
    int cb4 = rem >> 4;            // c-block 0..3
    int c0  = cb4 << 6;
    int hw0 = (rem & 15) << 6;
    int tid = threadIdx.x;
    int lane = tid & 31, wid = tid >> 5;

    #pragma unroll
    for (int i = 0; i < 16; ++i) {
        int cc = i * 4 + (tid >> 6);
        int hw = tid & 63;
        tile[cc][hw] = x[((size_t)b * C_ + c0 + cc) * HW_ + hw0 + hw];
    }
    __syncthreads();
    #pragma unroll
    for (int i = 0; i < 16; ++i) {
        int hh = i * 4 + (tid >> 6);
        int ci = tid & 63;
        float v = tile[ci][hh];
        __half h = __float2half_rn(v);
        __half m = __float2half_rn(v - __half2float(h));
        size_t o = (size_t)(b * HW_ + hw0 + hh) * C_ + c0 + ci;
        g_Ah[o] = h; g_Am[o] = m;

        float s = v * v;
        #pragma unroll
        for (int off = 16; off; off >>= 1) s += __shfl_xor_sync(0xffffffffu, s, off);
        if (lane == 0) w2[wid] = s;
        __syncthreads();
        if (lane == 0 && !(wid & 1))
            g_apart[cb4 * N_ + b * HW_ + hw0 + hh] = w2[wid] + w2[wid + 1];
        __syncthreads();
    }
}

// ---------------------------------------------------------------------------
// GEMM kernel: grid (256, 4). CTA: 128 M x 256 N, K = 256 (single fp16 plane).
// 8 warps (2M x 4N), warp tile 64x64, m16n8k16 fp16 HMMA, double-buffered
// cp.async K-chunks of 64. Epilogue: smem rowmin + global candidate lists.
// ---------------------------------------------------------------------------
#define APITCH 72
#define ABUF_B (128 * APITCH * 2)          // 18432
#define BBUF_B (256 * APITCH * 2)          // 36864
#define SM_GEMM (2 * ABUF_B + 2 * BBUF_B)  // 110592
#define NKC 4                              // K chunks (256/64)

__global__ __launch_bounds__(256, 1)
void vq_gemm_kernel()
{
    extern __shared__ __align__(16) char dsm[];
    const uint32_t smA = smem_u32(dsm);
    const uint32_t smB = smA + 2 * ABUF_B;

    __shared__ float sEn[256];
    __shared__ float sAv[128];
    __shared__ unsigned long long rowmin[128];

    const int tid  = threadIdx.x;
    const int lane = tid & 31;
    const int wid  = tid >> 5;
    const int wm   = wid >> 2;
    const int wn   = wid & 3;

    const int m0 = blockIdx.x << 7;     // 128 rows per CTA
    const int n0 = blockIdx.y << 8;     // 256 codes per CTA

    sEn[tid] = g_enorm[n0 + tid];
    if (tid < 128) {
        int n = m0 + tid;
        sAv[tid] = ((g_apart[n] + g_apart[N_ + n]) + g_apart[2 * N_ + n]) + g_apart[3 * N_ + n];
        rowmin[tid] = 0xFFFFFFFFFFFFFFFFull;
    }

    const __half* Ag = g_Ah + (size_t)m0 * C_;
    const __half* Bg = g_Bh + (size_t)n0 * C_;

    float acc[4][8][4];
    #pragma unroll
    for (int mf = 0; mf < 4; ++mf)
        #pragma unroll
        for (int nf = 0; nf < 8; ++nf)
            #pragma unroll
            for (int q = 0; q < 4; ++q) acc[mf][nf][q] = 0.f;

    const uint32_t aAddr0 = smA + (uint32_t)(((wm * 64 + (lane & 15)) * APITCH + ((lane >> 4) << 3)) * 2);
    const uint32_t bAddr0 = smB + (uint32_t)(((wn * 64 + (lane & 7) + ((lane >> 4) << 3)) * APITCH
                                              + (((lane >> 3) & 1) << 3)) * 2);

    // chunk loader: A = 128x64 (1024 x 16B), B = 256x64 (2048 x 16B)
    {
        #pragma unroll
        for (int j = 0; j < 4; ++j) {
            int p = tid + j * 256, row = p >> 3, kp = (p & 7) << 3;
            cp16(smA + (uint32_t)((row * APITCH + kp) * 2), Ag + (size_t)row * C_ + kp);
        }
        #pragma unroll
        for (int j = 0; j < 8; ++j) {
            int p = tid + j * 256, row = p >> 3, kp = (p & 7) << 3;
            cp16(smB + (uint32_t)((row * APITCH + kp) * 2), Bg + (size_t)row * C_ + kp);
        }
        CP_COMMIT();
    }

    for (int it = 0; it < NKC; ++it) {
        CP_WAIT0();
        __syncthreads();

        if (it + 1 < NKC) {
            const int nb = (it + 1) & 1;
            const int k0 = (it + 1) << 6;
            #pragma unroll
            for (int j = 0; j < 4; ++j) {
                int p = tid + j * 256, row = p >> 3, kp = (p & 7) << 3;
                cp16(smA + (uint32_t)(nb * ABUF_B + (row * APITCH + kp) * 2),
                     Ag + (size_t)row * C_ + k0 + kp);
            }
            #pragma unroll
            for (int j = 0; j < 8; ++j) {
                int p = tid + j * 256, row = p >> 3, kp = (p & 7) << 3;
                cp16(smB + (uint32_t)(nb * BBUF_B + (row * APITCH + kp) * 2),
                     Bg + (size_t)row * C_ + k0 + kp);
            }
            CP_COMMIT();
        }

        const int buf = it & 1;
        const uint32_t aB = aAddr0 + (uint32_t)(buf * ABUF_B);
        const uint32_t bB = bAddr0 + (uint32_t)(buf * BBUF_B);

        #pragma unroll
        for (int ks = 0; ks < 4; ++ks) {
            uint32_t a[4][4], bfr[4][4];
            #pragma unroll
            for (int mf = 0; mf < 4; ++mf)
                ldsm4(a[mf], aB + (uint32_t)(mf * 16 * APITCH * 2 + ks * 32));
            #pragma unroll
            for (int nb2 = 0; nb2 < 4; ++nb2)
                ldsm4(bfr[nb2], bB + (uint32_t)(nb2 * 16 * APITCH * 2 + ks * 32));
            #pragma unroll
            for (int mf = 0; mf < 4; ++mf)
                #pragma unroll
                for (int nf = 0; nf < 8; ++nf)
                    mma16816(acc[mf][nf], a[mf], &bfr[nf >> 1][(nf & 1) << 1]);
        }
    }

    // ---- epilogue: quantized approx distance, CTA-local rowmin, candidates --
    const int rb  = (wm << 6) + (lane >> 2);
    const int cl0 = (wn << 6) + ((lane & 3) << 1);
    #pragma unroll
    for (int mf = 0; mf < 4; ++mf) {
        #pragma unroll
        for (int half = 0; half < 2; ++half) {
            int lrow = rb + mf * 16 + half * 8;
            float a = sAv[lrow];
            unsigned long long lm = 0xFFFFFFFFFFFFFFFFull;
            #pragma unroll
            for (int nf = 0; nf < 8; ++nf) {
                int cl = cl0 + nf * 8;
                float s0 = (a + sEn[cl])     - 2.0f * acc[mf][nf][half * 2 + 0];
                float s1 = (a + sEn[cl + 1]) - 2.0f * acc[mf][nf][half * 2 + 1];
                acc[mf][nf][half * 2 + 0] = s0;
                acc[mf][nf][half * 2 + 1] = s1;
                unsigned long long p;
                p = ((unsigned long long)__float_as_uint(s0) << 32) | (unsigned)(n0 + cl);
                if (p < lm) lm = p;
                p = ((unsigned long long)__float_as_uint(s1) << 32) | (unsigned)(n0 + cl + 1);
                if (p < lm) lm = p;
            }
            atomicMin(&rowmin[lrow], lm);
        }
    }
    __syncthreads();
    #pragma unroll
    for (int mf = 0; mf < 4; ++mf) {
        #pragma unroll
        for (int half = 0; half < 2; ++half) {
            int lrow = rb + mf * 16 + half * 8;
            float thr = __uint_as_float((unsigned)(rowmin[lrow] >> 32)) + DELTA;
            int grow = m0 + lrow;
            #pragma unroll
            for (int nf = 0; nf < 8; ++nf) {
                int cl = cl0 + nf * 8;
                if (acc[mf][nf][half * 2 + 0] <= thr) {
                    int pos = atomicAdd(&g_cnt[grow], 1);
                    if (pos < CAP) g_cand[(size_t)grow * CAP + pos] = n0 + cl;
                }
                if (acc[mf][nf][half * 2 + 1] <= thr) {
                    int pos = atomicAdd(&g_cnt[grow], 1);
                    if (pos < CAP) g_cand[(size_t)grow * CAP + pos] = n0 + cl + 1;
                }
            }
        }
    }
}

// ---------------------------------------------------------------------------
// Recheck: 1 warp per row. Exact fp32 quantized distance for all candidates;
// packed (value, index) min = lowest index on ties. x reconstructed from the
// two fp16 planes (rel err <= 2^-22, flip-safe per R7/R8 evidence).
// ---------------------------------------------------------------------------
__global__ __launch_bounds__(256)
void recheck_kernel(const float* __restrict__ cb)
{
    __shared__ float xrow[8][256];
    const int lane = threadIdx.x & 31;
    const int wid  = threadIdx.x >> 5;
    const int row  = blockIdx.x * 8 + wid;

    {
        const __half* ah = g_Ah + (size_t)row * C_;
        const __half* am = g_Am + (size_t)row * C_;
        uint4 hv = *reinterpret_cast<const uint4*>(ah + lane * 8);
        uint4 mv = *reinterpret_cast<const uint4*>(am + lane * 8);
        const __half* hp = reinterpret_cast<const __half*>(&hv);
        const __half* mp = reinterpret_cast<const __half*>(&mv);
        #pragma unroll
        for (int j = 0; j < 8; ++j)
            xrow[wid][lane * 8 + j] = __half2float(hp[j]) + __half2float(mp[j]);
    }
    __syncwarp();

    int nct = g_cnt[row]; if (nct > CAP) nct = CAP;
    int n4 = row;
    float a = ((g_apart[n4] + g_apart[N_ + n4]) + g_apart[2 * N_ + n4]) + g_apart[3 * N_ + n4];
    const float* xr = xrow[wid];
    unsigned long long eb = 0xFFFFFFFFFFFFFFFFull;
    for (int j = lane; j < nct; j += 32) {
        int k = g_cand[(size_t)row * CAP + j];
        const float* cr = cb + (size_t)k * C_;
        float m2 = 0.f;
        #pragma unroll 8
        for (int c = 0; c < C_; ++c) m2 = fmaf(xr[c], cr[c], m2);
        float s = (a + g_enorm[k]) - 2.0f * m2;
        unsigned long long p =
            ((unsigned long long)__float_as_uint(s) << 32) | (unsigned)k;
        if (p < eb) eb = p;
    }
    #pragma unroll
    for (int off = 16; off; off >>= 1) {
        unsigned long long o = __shfl_xor_sync(0xffffffffu, eb, off);
        if (o < eb) eb = o;
    }
    if (lane == 0) g_idx[row] = (int)(unsigned)(eb & 0xFFFFFFFFull);
}

// ---------------------------------------------------------------------------
// Gather + straight-through output + loss (proven epilogue)
// ---------------------------------------------------------------------------
__global__ __launch_bounds__(256)
void gather_kernel(const float* __restrict__ x,
                   const float* __restrict__ cb,
                   float* __restrict__ out)
{
    __shared__ int   srow[128];
    __shared__ float wsum[8];

    const int tid = threadIdx.x;
    const int blk = blockIdx.x;
    const int b   = blk >> 3;
    const int hw0 = (blk & 7) << 7;
    const int m0  = blk << 7;

    if (tid < 128) {
        int idx = g_idx[m0 + tid];
        srow[tid] = idx;
        out[QSIZE + 1 + m0 + tid] = (float)idx;
    }
    __syncthreads();

    const float* xblk = x   + (size_t)b * (C_ * HW_) + hw0;
    float*       qblk = out + (size_t)b * (C_ * HW_) + hw0;
    float lsum = 0.f;
    #pragma unroll 4
    for (int it = 0; it < 32; ++it) {
        int l  = it * 256 + tid;
        int m4 = (l & 31) << 2;
        int c  = l >> 5;
        float4 xv = *reinterpret_cast<const float4*>(xblk + c * HW_ + m4);
        float q0 = __ldg(cb + (size_t)srow[m4 + 0] * C_ + c);
        float q1 = __ldg(cb + (size_t)srow[m4 + 1] * C_ + c);
        float q2 = __ldg(cb + (size_t)srow[m4 + 2] * C_ + c);
        float q3 = __ldg(cb + (size_t)srow[m4 + 3] * C_ + c);
        float d0 = q0 - xv.x, d1 = q1 - xv.y, d2 = q2 - xv.z, d3 = q3 - xv.w;
        float4 o;
        o.x = xv.x + d0; o.y = xv.y + d1; o.z = xv.z + d2; o.w = xv.w + d3;
        *reinterpret_cast<float4*>(qblk + c * HW_ + m4) = o;
        lsum += d0 * d0 + d1 * d1 + d2 * d2 + d3 * d3;
    }

    #pragma unroll
    for (int off = 16; off; off >>= 1)
        lsum += __shfl_xor_sync(0xffffffffu, lsum, off);
    if ((tid & 31) == 0) wsum[tid >> 5] = lsum;
    __syncthreads();
    if (tid == 0) {
        float s = 0.f;
        #pragma unroll
        for (int w = 0; w < 8; ++w) s += wsum[w];
        atomicAdd(&g_loss, s);
    }
}

extern "C" void kernel_launch(void* const* d_in, const int* in_sizes, int n_in,
                              void* d_out, int out_size) {
    (void)in_sizes; (void)n_in; (void)out_size;
    const float* x  = (const float*)d_in[0];
    const float* cb = (const float*)d_in[1];
    float* out = (float*)d_out;

    static bool attr_done = false;
    if (!attr_done) {
        cudaFuncSetAttribute(vq_gemm_kernel,
                             cudaFuncAttributeMaxDynamicSharedMemorySize, SM_GEMM);
        attr_done = true;
    }

    init_kernel<<<128, 256>>>();
    enorm_kernel<<<4, 256>>>(cb);
    prep_cb_kernel<<<1024, 256>>>(cb);
    prep_x_kernel<<<2048, 256>>>(x);
    {
        dim3 grid(256, 4);
        vq_gemm_kernel<<<grid, 256, SM_GEMM>>>();
    }
    recheck_kernel<<<4096, 256>>>(cb);
    gather_kernel<<<256, 256>>>(x, cb, out);
    finalize_kernel<<<1, 1>>>(out);
}

// round 11
// speedup vs baseline: 1.5484x; 1.0949x over previous
#include <cuda_runtime.h>
#include <cuda_fp16.h>
#include <cstdint>

// Problem constants
#define B_    32
#define C_    256
#define HW_   1024
#define N_    32768          // B_*HW_
#define K_    1024
#define QSIZE 8388608        // B_*C_*HW_
#define CAPS  16             // candidates per (row, n-slice)
#define DELTA 2.5e-3f

__device__ float g_enorm[K_];
__device__ float g_apart[4 * N_];           // per-64c-block partial |z|^2
__device__ float g_loss;
__device__ int   g_idx[N_];
__device__ int   g_cnt[N_ * 4];             // per (row, slice) candidate count
__device__ int   g_cand[(size_t)N_ * 4 * CAPS];
__device__ __half g_Ah[(size_t)N_ * C_];    // x rows hi plane, [n][256]
__device__ __half g_Am[(size_t)N_ * C_];    // x rows residual plane
__device__ __half g_Bh[(size_t)K_ * C_];    // codebook hi plane, [k][256]

// ---------------------------------------------------------------------------
// PTX helpers
// ---------------------------------------------------------------------------
__device__ __forceinline__ uint32_t smem_u32(const void* p) {
    uint32_t a;
    asm("{ .reg .u64 t; cvta.to.shared.u64 t, %1; cvt.u32.u64 %0, t; }" : "=r"(a) : "l"(p));
    return a;
}
__device__ __forceinline__ void cp16(uint32_t daddr, const void* g) {
    asm volatile("cp.async.cg.shared.global [%0], [%1], 16;" :: "r"(daddr), "l"(g));
}
#define CP_COMMIT()  asm volatile("cp.async.commit_group;")
#define CP_WAIT0()   asm volatile("cp.async.wait_group 0;")

__device__ __forceinline__ void ldsm4(uint32_t* r, uint32_t addr) {
    asm volatile("ldmatrix.sync.aligned.m8n8.x4.shared.b16 {%0,%1,%2,%3}, [%4];"
        : "=r"(r[0]), "=r"(r[1]), "=r"(r[2]), "=r"(r[3]) : "r"(addr));
}
__device__ __forceinline__ void mma16816(float* d, const uint32_t* a, const uint32_t* b) {
    asm volatile(
        "mma.sync.aligned.m16n8k16.row.col.f32.f16.f16.f32 "
        "{%0,%1,%2,%3},{%4,%5,%6,%7},{%8,%9},{%0,%1,%2,%3};"
        : "+f"(d[0]), "+f"(d[1]), "+f"(d[2]), "+f"(d[3])
        : "r"(a[0]), "r"(a[1]), "r"(a[2]), "r"(a[3]), "r"(b[0]), "r"(b[1]));
}

// ---------------------------------------------------------------------------
// Launch #1: codebook -> fp16 plane; blocks 0-3 also compute enorm (order-
// identical to the R2-passing sequential-quartet accumulation).
// ---------------------------------------------------------------------------
__global__ void prep_cb_kernel(const float* __restrict__ cb) {
    int i = blockIdx.x * blockDim.x + threadIdx.x;   // 0 .. 262143
    g_Bh[i] = __float2half_rn(cb[i]);
    if (blockIdx.x < 4) {
        int k = blockIdx.x * blockDim.x + threadIdx.x;
        const float4* row = reinterpret_cast<const float4*>(cb + (size_t)k * C_);
        float s = 0.f;
        #pragma unroll
        for (int q = 0; q < C_ / 4; ++q) {
            float4 v = row[q];
            s += v.x * v.x + v.y * v.y + v.z * v.z + v.w * v.w;
        }
        g_enorm[k] = s;
    }
}

// ---------------------------------------------------------------------------
// Launch #2: transpose x -> 2 fp16 planes + deterministic |z|^2 partials.
// ---------------------------------------------------------------------------
__global__ void prep_x_kernel(const float* __restrict__ x) {
    __shared__ float tile[64][65];
    __shared__ float w2[8];
    int bid = blockIdx.x;          // 2048 blocks
    int b   = bid >> 6;
    int rem = bid & 63;
    int cb4 = rem >> 4;            // c-block 0..3
    int c0  = cb4 << 6;
    int hw0 = (rem & 15) << 6;
    int tid = threadIdx.x;
    int lane = tid & 31, wid = tid >> 5;

    #pragma unroll
    for (int i = 0; i < 16; ++i) {
        int cc = i * 4 + (tid >> 6);
        int hw = tid & 63;
        tile[cc][hw] = x[((size_t)b * C_ + c0 + cc) * HW_ + hw0 + hw];
    }
    __syncthreads();
    #pragma unroll
    for (int i = 0; i < 16; ++i) {
        int hh = i * 4 + (tid >> 6);
        int ci = tid & 63;
        float v = tile[ci][hh];
        __half h = __float2half_rn(v);
        __half m = __float2half_rn(v - __half2float(h));
        size_t o = (size_t)(b * HW_ + hw0 + hh) * C_ + c0 + ci;
        g_Ah[o] = h; g_Am[o] = m;

        float s = v * v;
        #pragma unroll
        for (int off = 16; off; off >>= 1) s += __shfl_xor_sync(0xffffffffu, s, off);
        if (lane == 0) w2[wid] = s;
        __syncthreads();
        if (lane == 0 && !(wid & 1))
            g_apart[cb4 * N_ + b * HW_ + hw0 + hh] = w2[wid] + w2[wid + 1];
        __syncthreads();
    }
}

// Launch #3 (keeps GEMM at profiled launch index #4)
__global__ void zero_loss_kernel() { g_loss = 0.0f; }

// ---------------------------------------------------------------------------
// Launch #4: GEMM. grid (256, 4). CTA: 128 M x 256 N, K = 256 fp16.
// Single-pass epilogue: acc -> fp16 screen values in smem (acc dies, no
// spill), then per-row smem scan -> screen min + candidate lists (no atomics).
// ---------------------------------------------------------------------------
#define APITCH 72
#define ABUF_B (128 * APITCH * 2)          // 18432
#define BBUF_B (256 * APITCH * 2)          // 36864
#define SDIST_OFF (2 * ABUF_B + 2 * BBUF_B)        // 110592
#define DPITCH 258                                  // halves; 516B = 129 words -> conflict-free
#define SM_GEMM (SDIST_OFF + 128 * DPITCH * 2)      // 176640
#define NKC 4

__global__ __launch_bounds__(256, 1)
void vq_gemm_kernel()
{
    extern __shared__ __align__(16) char dsm[];
    const uint32_t smA = smem_u32(dsm);
    const uint32_t smB = smA + 2 * ABUF_B;

    __shared__ float sEn[256];

    const int tid  = threadIdx.x;
    const int lane = tid & 31;
    const int wid  = tid >> 5;
    const int wm   = wid >> 2;
    const int wn   = wid & 3;

    const int m0 = blockIdx.x << 7;     // 128 rows per CTA
    const int n0 = blockIdx.y << 8;     // 256 codes per CTA

    sEn[tid] = g_enorm[n0 + tid];

    const __half* Ag = g_Ah + (size_t)m0 * C_;
    const __half* Bg = g_Bh + (size_t)n0 * C_;

    float acc[4][8][4];
    #pragma unroll
    for (int mf = 0; mf < 4; ++mf)
        #pragma unroll
        for (int nf = 0; nf < 8; ++nf)
            #pragma unroll
            for (int q = 0; q < 4; ++q) acc[mf][nf][q] = 0.f;

    const uint32_t aAddr0 = smA + (uint32_t)(((wm * 64 + (lane & 15)) * APITCH + ((lane >> 4) << 3)) * 2);
    const uint32_t bAddr0 = smB + (uint32_t)(((wn * 64 + (lane & 7) + ((lane >> 4) << 3)) * APITCH
                                              + (((lane >> 3) & 1) << 3)) * 2);

    {
        #pragma unroll
        for (int j = 0; j < 4; ++j) {
            int p = tid + j * 256, row = p >> 3, kp = (p & 7) << 3;
            cp16(smA + (uint32_t)((row * APITCH + kp) * 2), Ag + (size_t)row * C_ + kp);
        }
        #pragma unroll
        for (int j = 0; j < 8; ++j) {
            int p = tid + j * 256, row = p >> 3, kp = (p & 7) << 3;
            cp16(smB + (uint32_t)((row * APITCH + kp) * 2), Bg + (size_t)row * C_ + kp);
        }
        CP_COMMIT();
    }

    for (int it = 0; it < NKC; ++it) {
        CP_WAIT0();
        __syncthreads();

        if (it + 1 < NKC) {
            const int nb = (it + 1) & 1;
            const int k0 = (it + 1) << 6;
            #pragma unroll
            for (int j = 0; j < 4; ++j) {
                int p = tid + j * 256, row = p >> 3, kp = (p & 7) << 3;
                cp16(smA + (uint32_t)(nb * ABUF_B + (row * APITCH + kp) * 2),
                     Ag + (size_t)row * C_ + k0 + kp);
            }
            #pragma unroll
            for (int j = 0; j < 8; ++j) {
                int p = tid + j * 256, row = p >> 3, kp = (p & 7) << 3;
                cp16(smB + (uint32_t)(nb * BBUF_B + (row * APITCH + kp) * 2),
                     Bg + (size_t)row * C_ + k0 + kp);
            }
            CP_COMMIT();
        }

        const int buf = it & 1;
        const uint32_t aB = aAddr0 + (uint32_t)(buf * ABUF_B);
        const uint32_t bB = bAddr0 + (uint32_t)(buf * BBUF_B);

        #pragma unroll
        for (int ks = 0; ks < 4; ++ks) {
            uint32_t a[4][4], bfr[4][4];
            #pragma unroll
            for (int mf = 0; mf < 4; ++mf)
                ldsm4(a[mf], aB + (uint32_t)(mf * 16 * APITCH * 2 + ks * 32));
            #pragma unroll
            for (int nb2 = 0; nb2 < 4; ++nb2)
                ldsm4(bfr[nb2], bB + (uint32_t)(nb2 * 16 * APITCH * 2 + ks * 32));
            #pragma unroll
            for (int mf = 0; mf < 4; ++mf)
                #pragma unroll
                for (int nf = 0; nf < 8; ++nf)
                    mma16816(acc[mf][nf], a[mf], &bfr[nf >> 1][(nf & 1) << 1]);
        }
    }

    // ---- single-pass epilogue: t = e - 2m -> fp16 smem (acc dies here) -----
    const int rb  = (wm << 6) + (lane >> 2);
    const int cl0 = (wn << 6) + ((lane & 3) << 1);
    #pragma unroll
    for (int mf = 0; mf < 4; ++mf) {
        #pragma unroll
        for (int hv = 0; hv < 2; ++hv) {
            int lrow = rb + mf * 16 + hv * 8;
            #pragma unroll
            for (int nf = 0; nf < 8; ++nf) {
                int cl = cl0 + nf * 8;
                float t0 = fmaf(-2.0f, acc[mf][nf][hv * 2 + 0], sEn[cl]);
                float t1 = fmaf(-2.0f, acc[mf][nf][hv * 2 + 1], sEn[cl + 1]);
                *reinterpret_cast<__half2*>(dsm + SDIST_OFF + ((size_t)lrow * DPITCH + cl) * 2)
                    = __floats2half2_rn(t0, t1);
            }
        }
    }
    __syncthreads();

    // ---- per-row scan: screen min + candidates (thread tid owns row tid) ----
    if (tid < 128) {
        const __half2* rowp =
            reinterpret_cast<const __half2*>(dsm + SDIST_OFF + (size_t)tid * DPITCH * 2);
        float mn = 3.4e38f;
        #pragma unroll 8
        for (int i = 0; i < 128; ++i) {
            __half2 h2 = rowp[i];
            float f0 = __low2float(h2), f1 = __high2float(h2);
            if (f0 < mn) mn = f0;
            if (f1 < mn) mn = f1;
        }
        float thr = mn + DELTA;
        int slot = ((m0 + tid) * 4 + blockIdx.y);
        int* cl = g_cand + (size_t)slot * CAPS;
        int cnt = 0;
        #pragma unroll 8
        for (int i = 0; i < 128; ++i) {
            __half2 h2 = rowp[i];
            float f0 = __low2float(h2), f1 = __high2float(h2);
            if (f0 <= thr && cnt < CAPS) cl[cnt++] = n0 + 2 * i;
            if (f1 <= thr && cnt < CAPS) cl[cnt++] = n0 + 2 * i + 1;
        }
        g_cnt[slot] = cnt;
    }
}

// ---------------------------------------------------------------------------
// Launch #5: recheck. 1 warp per row: exact fp32 quantized distance for all
// candidates from the 4 slices; packed (value,index) min = lowest index ties.
// ---------------------------------------------------------------------------
__global__ __launch_bounds__(256)
void recheck_kernel(const float* __restrict__ cb)
{
    __shared__ float xrow[8][256];
    __shared__ int   cands[8][4 * CAPS];
    const int lane = threadIdx.x & 31;
    const int wid  = threadIdx.x >> 5;
    const int row  = blockIdx.x * 8 + wid;

    {
        const __half* ah = g_Ah + (size_t)row * C_;
        const __half* am = g_Am + (size_t)row * C_;
        uint4 hvv = *reinterpret_cast<const uint4*>(ah + lane * 8);
        uint4 mvv = *reinterpret_cast<const uint4*>(am + lane * 8);
        const __half* hp = reinterpret_cast<const __half*>(&hvv);
        const __half* mp = reinterpret_cast<const __half*>(&mvv);
        #pragma unroll
        for (int j = 0; j < 8; ++j)
            xrow[wid][lane * 8 + j] = __half2float(hp[j]) + __half2float(mp[j]);
    }

    // gather candidate union into smem
    int nct = 0;
    #pragma unroll
    for (int y = 0; y < 4; ++y) {
        int slot = row * 4 + y;
        int cy = g_cnt[slot];
        if (lane < cy) cands[wid][nct + lane] = g_cand[(size_t)slot * CAPS + lane];
        nct += cy;
    }
    __syncwarp();

    float a = ((g_apart[row] + g_apart[N_ + row]) + g_apart[2 * N_ + row]) + g_apart[3 * N_ + row];
    const float* xr = xrow[wid];
    unsigned long long eb = 0xFFFFFFFFFFFFFFFFull;
    for (int j = lane; j < nct; j += 32) {
        int k = cands[wid][j];
        const float* cr = cb + (size_t)k * C_;
        float m2 = 0.f;
        #pragma unroll 8
        for (int c = 0; c < C_; ++c) m2 = fmaf(xr[c], cr[c], m2);
        float s = (a + g_enorm[k]) - 2.0f * m2;
        unsigned long long p =
            ((unsigned long long)__float_as_uint(s) << 32) | (unsigned)k;
        if (p < eb) eb = p;
    }
    #pragma unroll
    for (int off = 16; off; off >>= 1) {
        unsigned long long o = __shfl_xor_sync(0xffffffffu, eb, off);
        if (o < eb) eb = o;
    }
    if (lane == 0) g_idx[row] = (int)(unsigned)(eb & 0xFFFFFFFFull);
}

// ---------------------------------------------------------------------------
// Launch #6: gather + straight-through output + loss (proven epilogue)
// ---------------------------------------------------------------------------
__global__ __launch_bounds__(256)
void gather_kernel(const float* __restrict__ x,
                   const float* __restrict__ cb,
                   float* __restrict__ out)
{
    __shared__ int   srow[128];
    __shared__ float wsum[8];

    const int tid = threadIdx.x;
    const int blk = blockIdx.x;
    const int b   = blk >> 3;
    const int hw0 = (blk & 7) << 7;
    const int m0  = blk << 7;

    if (tid < 128) {
        int idx = g_idx[m0 + tid];
        srow[tid] = idx;
        out[QSIZE + 1 + m0 + tid] = (float)idx;
    }
    __syncthreads();

    const float* xblk = x   + (size_t)b * (C_ * HW_) + hw0;
    float*       qblk = out + (size_t)b * (C_ * HW_) + hw0;
    float lsum = 0.f;
    #pragma unroll 4
    for (int it = 0; it < 32; ++it) {
        int l  = it * 256 + tid;
        int m4 = (l & 31) << 2;
        int c  = l >> 5;
        float4 xv = *reinterpret_cast<const float4*>(xblk + c * HW_ + m4);
        float q0 = __ldg(cb + (size_t)srow[m4 + 0] * C_ + c);
        float q1 = __ldg(cb + (size_t)srow[m4 + 1] * C_ + c);
        float q2 = __ldg(cb + (size_t)srow[m4 + 2] * C_ + c);
        float q3 = __ldg(cb + (size_t)srow[m4 + 3] * C_ + c);
        float d0 = q0 - xv.x, d1 = q1 - xv.y, d2 = q2 - xv.z, d3 = q3 - xv.w;
        float4 o;
        o.x = xv.x + d0; o.y = xv.y + d1; o.z = xv.z + d2; o.w = xv.w + d3;
        *reinterpret_cast<float4*>(qblk + c * HW_ + m4) = o;
        lsum += d0 * d0 + d1 * d1 + d2 * d2 + d3 * d3;
    }

    #pragma unroll
    for (int off = 16; off; off >>= 1)
        lsum += __shfl_xor_sync(0xffffffffu, lsum, off);
    if ((tid & 31) == 0) wsum[tid >> 5] = lsum;
    __syncthreads();
    if (tid == 0) {
        float s = 0.f;
        #pragma unroll
        for (int w = 0; w < 8; ++w) s += wsum[w];
        atomicAdd(&g_loss, s);
    }
}

__global__ void finalize_kernel(float* __restrict__ out) {
    out[QSIZE] = 1.25f * g_loss * (1.0f / (float)QSIZE);
}

extern "C" void kernel_launch(void* const* d_in, const int* in_sizes, int n_in,
                              void* d_out, int out_size) {
    (void)in_sizes; (void)n_in; (void)out_size;
    const float* x  = (const float*)d_in[0];
    const float* cb = (const float*)d_in[1];
    float* out = (float*)d_out;

    static bool attr_done = false;
    if (!attr_done) {
        cudaFuncSetAttribute(vq_gemm_kernel,
                             cudaFuncAttributeMaxDynamicSharedMemorySize, SM_GEMM);
        attr_done = true;
    }

    prep_cb_kernel<<<1024, 256>>>(cb);       // #1
    prep_x_kernel<<<2048, 256>>>(x);         // #2
    zero_loss_kernel<<<1, 1>>>();            // #3
    {
        dim3 grid(256, 4);
        vq_gemm_kernel<<<grid, 256, SM_GEMM>>>();   // #4 (profiled)
    }
    recheck_kernel<<<4096, 256>>>(cb);       // #5
    gather_kernel<<<256, 256>>>(x, cb, out); // #6
    finalize_kernel<<<1, 1>>>(out);          // #7
}